// round 15
// baseline (speedup 1.0000x reference)
#include <cuda_runtime.h>
#include <cuda_bf16.h>
#include <cstdint>

#define DIMK 2048
#define NEXP 64
#define BM   128             // tokens per CTA
#define NT   256             // 8 warps: 2 k-groups x 4 warps (warp tile m32 x n64)
#define KCH  16              // k per chunk
#define NCHG 64              // chunks per group (1024/16)
#define ROWB 48              // padded row bytes (12r mod 32 distinct -> conflict-free ldm)
#define DELTA 1e-4f
#define FCAP 64              // per-CTA flagged-token capacity
#define RSTRIDE4 (32 * (DIMK / 4))   // float4 stride between 32-row groups (16384)

// per-stage layout (bytes within a group region) — 3 stages
#define A_HI 0
#define A_LO 6144
#define B_HI 12288
#define B_LO 15360
#define STAGEB 18432
#define NSTG 3
#define GROUPB (NSTG * STAGEB)   // 55296
#define SMEMB  (2 * GROUPB)      // 110592 total dynamic smem
#define RED_STRIDE 68            // reduction row stride in floats (34816B < GROUPB)

// ---------- helpers ----------
__device__ __forceinline__ uint32_t smem_u32(const void* p) {
    uint32_t a;
    asm("{ .reg .u64 t; cvta.to.shared.u64 t, %1; cvt.u32.u64 %0, t; }" : "=r"(a) : "l"(p));
    return a;
}
__device__ __forceinline__ void gbar(int id) {
    asm volatile("bar.sync %0, %1;" :: "r"(id), "r"(128) : "memory");
}
__device__ __forceinline__ void sts64(uint32_t a, uint32_t x, uint32_t y) {
    asm volatile("st.shared.v2.b32 [%0], {%1,%2};" :: "r"(a), "r"(x), "r"(y) : "memory");
}
__device__ __forceinline__ void ldm4(uint32_t addr, uint32_t* r) {
    asm volatile("ldmatrix.sync.aligned.m8n8.x4.shared.b16 {%0,%1,%2,%3}, [%4];"
                 : "=r"(r[0]), "=r"(r[1]), "=r"(r[2]), "=r"(r[3]) : "r"(addr));
}
__device__ __forceinline__ void mma16(float* c, const uint32_t* a, uint32_t b0, uint32_t b1) {
    asm volatile(
        "mma.sync.aligned.m16n8k16.row.col.f32.bf16.bf16.f32 "
        "{%0,%1,%2,%3}, {%4,%5,%6,%7}, {%8,%9}, {%0,%1,%2,%3};"
        : "+f"(c[0]), "+f"(c[1]), "+f"(c[2]), "+f"(c[3])
        : "r"(a[0]), "r"(a[1]), "r"(a[2]), "r"(a[3]), "r"(b0), "r"(b1));
}
// fp32x4 -> (hi bf16, lo bf16), packed 2 uints each
__device__ __forceinline__ void split4(float4 v, uint32_t* hu, uint32_t* lu) {
    __nv_bfloat16 hx = __float2bfloat16_rn(v.x);
    __nv_bfloat16 hy = __float2bfloat16_rn(v.y);
    __nv_bfloat16 hz = __float2bfloat16_rn(v.z);
    __nv_bfloat16 hw = __float2bfloat16_rn(v.w);
    __nv_bfloat16 lx = __float2bfloat16_rn(v.x - __bfloat162float(hx));
    __nv_bfloat16 ly = __float2bfloat16_rn(v.y - __bfloat162float(hy));
    __nv_bfloat16 lz = __float2bfloat16_rn(v.z - __bfloat162float(hz));
    __nv_bfloat16 lw = __float2bfloat16_rn(v.w - __bfloat162float(hw));
    hu[0] = (uint32_t)__bfloat16_as_ushort(hx) | ((uint32_t)__bfloat16_as_ushort(hy) << 16);
    hu[1] = (uint32_t)__bfloat16_as_ushort(hz) | ((uint32_t)__bfloat16_as_ushort(hw) << 16);
    lu[0] = (uint32_t)__bfloat16_as_ushort(lx) | ((uint32_t)__bfloat16_as_ushort(ly) << 16);
    lu[1] = (uint32_t)__bfloat16_as_ushort(lz) | ((uint32_t)__bfloat16_as_ushort(lw) << 16);
}

// one k16 chunk of 3-pass MMA for this warp, reading stage at byte offset stg
__device__ __forceinline__ void compute_chunk(uint32_t gb, uint32_t stg,
                                              uint32_t a_off, uint32_t b_off,
                                              float acc[2][8][4]) {
    const uint32_t abase = gb + stg + A_HI + a_off;
    const uint32_t bbase = gb + stg + B_HI + b_off;
    uint32_t ah[2][4], al[2][4];
#pragma unroll
    for (int i = 0; i < 2; i++) {
        ldm4(abase + (uint32_t)(i * 16 * ROWB), ah[i]);
        ldm4(abase + (uint32_t)(i * 16 * ROWB) + (A_LO - A_HI), al[i]);
    }
#pragma unroll
    for (int jp = 0; jp < 4; jp++) {
        uint32_t th[4], tl4[4];
        ldm4(bbase + (uint32_t)(jp * 16 * ROWB), th);
        ldm4(bbase + (uint32_t)(jp * 16 * ROWB) + (B_LO - B_HI), tl4);
#pragma unroll
        for (int i = 0; i < 2; i++) {
            mma16(acc[i][2 * jp],     ah[i], th[0],  th[1]);    // hh
            mma16(acc[i][2 * jp],     al[i], th[0],  th[1]);    // lh
            mma16(acc[i][2 * jp],     ah[i], tl4[0], tl4[1]);   // hl
            mma16(acc[i][2 * jp + 1], ah[i], th[2],  th[3]);
            mma16(acc[i][2 * jp + 1], al[i], th[2],  th[3]);
            mma16(acc[i][2 * jp + 1], ah[i], tl4[2], tl4[3]);
        }
    }
}

struct Top3 { float v0, v1, v2; int i0, i1; };
__device__ __forceinline__ void t3_insert(Top3& t, float v, int i) {
    if (v > t.v0 || (v == t.v0 && i < t.i0)) {
        t.v2 = t.v1; t.v1 = t.v0; t.i1 = t.i0; t.v0 = v; t.i0 = i;
    } else if (v > t.v1 || (v == t.v1 && i < t.i1)) {
        t.v2 = t.v1; t.v1 = v; t.i1 = i;
    } else if (v > t.v2) {
        t.v2 = v;
    }
}
__device__ __forceinline__ void t3_merge_xor(Top3& t, int m) {
    float pv0 = __shfl_xor_sync(0xFFFFFFFFu, t.v0, m);
    float pv1 = __shfl_xor_sync(0xFFFFFFFFu, t.v1, m);
    float pv2 = __shfl_xor_sync(0xFFFFFFFFu, t.v2, m);
    int   pi0 = __shfl_xor_sync(0xFFFFFFFFu, t.i0, m);
    int   pi1 = __shfl_xor_sync(0xFFFFFFFFu, t.i1, m);
    t3_insert(t, pv0, pi0);
    t3_insert(t, pv1, pi1);
    t3_insert(t, pv2, 0x40000000);
}

// =========================================================================
// Single kernel: 3-pass hi/lo bf16 GEMM (2 k-groups, warp tile m32n64),
// 3-stage single-barrier pipeline, coalesced fill, top-2 epilogue,
// in-CTA exact repair of low-margin tokens.
// =========================================================================
__global__ __launch_bounds__(NT, 2)
void router_mma(const float* __restrict__ x,
                const float* __restrict__ w,
                float* __restrict__ out_mask,
                float* __restrict__ out_w,
                float* __restrict__ out_i)
{
    extern __shared__ char smem[];
    const uint32_t smb = smem_u32(smem);

    __shared__ int s_cnt;
    __shared__ int s_list[FCAP];

    const int tid   = threadIdx.x;
    const int lane  = tid & 31;
    const int wid   = tid >> 5;        // 0..7
    const int grp   = wid >> 2;        // k-group 0/1
    const int wid_l = wid & 3;         // warp within group
    const int tl    = tid & 127;       // fill id within group
    const int gr    = lane >> 2;
    const int gc    = lane & 3;
    const int mbase = blockIdx.x * BM;
    const int barid = grp + 1;

    if (tid == 0) s_cnt = 0;

    const uint32_t gb = smb + (uint32_t)grp * GROUPB;

    // ---- coalesced fill assignment: 4 lanes per row, 8 rows/warp/instr ----
    const int frow = tl >> 2;          // base row 0..31 (A rows +32q, B rows +32q)
    const int fcol = tl & 3;           // float4 slot within the 64B chunk segment
    const float4* xr = (const float4*)(x + (size_t)(mbase + frow) * DIMK) + grp * 256 + fcol;
    const float4* wr = (const float4*)(w + (size_t)frow * DIMK) + grp * 256 + fcol;
    const uint32_t aQ0 = gb + A_HI + (uint32_t)(frow * ROWB + fcol * 8);
    const uint32_t bQ0 = gb + B_HI + (uint32_t)(frow * ROWB + fcol * 8);

    // ---- ldmatrix lane offsets (proven mapping) ----
    const uint32_t a_off = (uint32_t)((wid_l * 32 + ((lane >> 3) & 1) * 8 + (lane & 7)) * ROWB
                                      + (lane >> 4) * 16);
    const uint32_t b_off = (uint32_t)(((((lane >> 4) & 1) * 8) + (lane & 7)) * ROWB
                                      + ((lane >> 3) & 1) * 16);

    float acc[2][8][4];
#pragma unroll
    for (int i = 0; i < 2; i++)
#pragma unroll
        for (int j = 0; j < 8; j++)
#pragma unroll
            for (int r = 0; r < 4; r++) acc[i][j][r] = 0.0f;

    // ---- prefetch chunk 0 into registers ----
    float4 pa[4], pb[2];
#pragma unroll
    for (int q = 0; q < 4; q++) pa[q] = xr[q * RSTRIDE4];
    pb[0] = wr[0];
    pb[1] = wr[RSTRIDE4];

    // ---- 3-stage, one barrier per chunk:
    //      STS(c) ; LDG(c+1) ; compute(c-1) ; bar  ----
    int sc = 0;
    uint32_t stgP = 0;
#pragma unroll 1
    for (int c = 0; c < NCHG; c++) {
        const uint32_t stgC = (uint32_t)(sc * STAGEB);

        // ---- publish chunk c from registers ----
        {
            uint32_t h[2], l[2];
#pragma unroll
            for (int q = 0; q < 4; q++) {
                split4(pa[q], h, l);
                sts64(aQ0 + (uint32_t)(q * 32 * ROWB) + stgC, h[0], h[1]);
                sts64(aQ0 + (uint32_t)(q * 32 * ROWB) + stgC + (A_LO - A_HI), l[0], l[1]);
            }
#pragma unroll
            for (int q = 0; q < 2; q++) {
                split4(pb[q], h, l);
                sts64(bQ0 + (uint32_t)(q * 32 * ROWB) + stgC, h[0], h[1]);
                sts64(bQ0 + (uint32_t)(q * 32 * ROWB) + stgC + (B_LO - B_HI), l[0], l[1]);
            }
        }

        // ---- prefetch chunk c+1 (regs free after STS above) ----
        if (c + 1 < NCHG) {
#pragma unroll
            for (int q = 0; q < 4; q++) pa[q] = xr[(c + 1) * 4 + q * RSTRIDE4];
            pb[0] = wr[(c + 1) * 4];
            pb[1] = wr[(c + 1) * 4 + RSTRIDE4];
        }

        // ---- compute chunk c-1 (its stage is fully published & visible) ----
        if (c > 0) compute_chunk(gb, stgP, a_off, b_off, acc);

        gbar(barid);

        stgP = stgC;
        sc = (sc == NSTG - 1) ? 0 : sc + 1;
    }
    // final chunk
    compute_chunk(gb, stgP, a_off, b_off, acc);

    // ---- cross-group reduction (group 1 -> smem -> group 0 adds) ----
    __syncthreads();
    float* redf = (float*)(smem + GROUPB);
    if (grp == 1) {
#pragma unroll
        for (int i = 0; i < 2; i++)
#pragma unroll
            for (int rh = 0; rh < 2; rh++) {
                const int ml = wid_l * 32 + i * 16 + rh * 8 + gr;
#pragma unroll
                for (int j = 0; j < 8; j++) {
                    float2 v = make_float2(acc[i][j][rh * 2], acc[i][j][rh * 2 + 1]);
                    *(float2*)(redf + ml * RED_STRIDE + 8 * j + 2 * gc) = v;
                }
            }
    }
    __syncthreads();
    if (grp == 0) {
#pragma unroll
        for (int i = 0; i < 2; i++)
#pragma unroll
            for (int rh = 0; rh < 2; rh++) {
                const int ml = wid_l * 32 + i * 16 + rh * 8 + gr;
#pragma unroll
                for (int j = 0; j < 8; j++) {
                    float2 v = *(float2*)(redf + ml * RED_STRIDE + 8 * j + 2 * gc);
                    acc[i][j][rh * 2]     += v.x;
                    acc[i][j][rh * 2 + 1] += v.y;
                }
            }

        // ---- epilogue: top-2 + smem flags + outputs ----
#pragma unroll
        for (int i = 0; i < 2; i++) {
#pragma unroll
            for (int rh = 0; rh < 2; rh++) {
                const int m = wid_l * 32 + i * 16 + rh * 8 + gr;
                Top3 t; t.v0 = -1e30f; t.v1 = -1e30f; t.v2 = -1e30f; t.i0 = 0; t.i1 = 0;
#pragma unroll
                for (int j = 0; j < 8; j++) {
#pragma unroll
                    for (int b = 0; b < 2; b++)
                        t3_insert(t, acc[i][j][rh * 2 + b], 8 * j + 2 * gc + b);
                }
                t3_merge_xor(t, 1);
                t3_merge_xor(t, 2);

                const size_t g = (size_t)(mbase + m);
                if (gc == 0) {
                    float e1  = expf(t.v1 - t.v0);
                    float inv = 1.0f / (1.0f + e1);
                    out_w[g * 2 + 0] = inv;
                    out_w[g * 2 + 1] = e1 * inv;
                    out_i[g * 2 + 0] = (float)t.i0;
                    out_i[g * 2 + 1] = (float)t.i1;
                    if ((t.v0 - t.v1 < DELTA) || (t.v1 - t.v2 < DELTA)) {
                        int slot = atomicAdd(&s_cnt, 1);
                        if (slot < FCAP) s_list[slot] = m;
                    }
                }
                float* mrow = out_mask + g * NEXP + gc * 16;
#pragma unroll
                for (int q = 0; q < 4; q++) {
                    int e0 = gc * 16 + q * 4;
                    float4 mv;
                    mv.x = (e0 + 0 == t.i0 || e0 + 0 == t.i1) ? 1.0f : 0.0f;
                    mv.y = (e0 + 1 == t.i0 || e0 + 1 == t.i1) ? 1.0f : 0.0f;
                    mv.z = (e0 + 2 == t.i0 || e0 + 2 == t.i1) ? 1.0f : 0.0f;
                    mv.w = (e0 + 3 == t.i0 || e0 + 3 == t.i1) ? 1.0f : 0.0f;
                    *(float4*)(mrow + q * 4) = mv;
                }
            }
        }
    }

    // ================= in-CTA exact repair of flagged tokens =================
    __syncthreads();
    int cnt = s_cnt;
    if (cnt > FCAP) cnt = FCAP;
    if (cnt > 0) {
        float* xs = (float*)smem;            // 8KB, stage area is dead now
        float* lg = (float*)(smem + 8192);   // 64 floats
        const int e    = tid >> 2;           // expert
        const int part = tid & 3;            // interleaved float4 k-part

        for (int it = 0; it < cnt; it++) {
            const int m = s_list[it];
            const size_t tok = (size_t)(mbase + m);
            __syncthreads();
            {
                const float4* xrow = (const float4*)(x + tok * DIMK);
                for (int q = tid; q < DIMK / 4; q += NT)
                    ((float4*)xs)[q] = xrow[q];
            }
            __syncthreads();

            const float4* wrow = (const float4*)(w + (size_t)e * DIMK);
            const float4* xp   = (const float4*)xs;
            float4 accv = make_float4(0, 0, 0, 0);
#pragma unroll 8
            for (int q = 0; q < 128; q++) {
                float4 xv = xp[4 * q + part];
                float4 wv = wrow[4 * q + part];
                accv.x = fmaf(xv.x, wv.x, accv.x);
                accv.y = fmaf(xv.y, wv.y, accv.y);
                accv.z = fmaf(xv.z, wv.z, accv.z);
                accv.w = fmaf(xv.w, wv.w, accv.w);
            }
            float s = (accv.x + accv.y) + (accv.z + accv.w);
            s += __shfl_xor_sync(0xFFFFFFFFu, s, 1);
            s += __shfl_xor_sync(0xFFFFFFFFu, s, 2);
            if (part == 0) lg[e] = s;
            __syncthreads();

            if (tid < 32) {
                Top3 t; t.v0 = -1e30f; t.v1 = -1e30f; t.v2 = -1e30f; t.i0 = 0; t.i1 = 0;
                t3_insert(t, lg[tid], tid);
                t3_insert(t, lg[tid + 32], tid + 32);
                t3_merge_xor(t, 1);
                t3_merge_xor(t, 2);
                t3_merge_xor(t, 4);
                t3_merge_xor(t, 8);
                t3_merge_xor(t, 16);

                int i0 = __shfl_sync(0xFFFFFFFFu, t.i0, 0);
                int i1 = __shfl_sync(0xFFFFFFFFu, t.i1, 0);
                if (tid == 0) {
                    float e1  = expf(t.v1 - t.v0);
                    float inv = 1.0f / (1.0f + e1);
                    out_w[tok * 2 + 0] = inv;
                    out_w[tok * 2 + 1] = e1 * inv;
                    out_i[tok * 2 + 0] = (float)i0;
                    out_i[tok * 2 + 1] = (float)i1;
                }
                out_mask[tok * NEXP + tid] =
                    (tid == i0 || tid == i1) ? 1.0f : 0.0f;
                out_mask[tok * NEXP + tid + 32] =
                    (tid + 32 == i0 || tid + 32 == i1) ? 1.0f : 0.0f;
            }
        }
    }
}

extern "C" void kernel_launch(void* const* d_in, const int* in_sizes, int n_in,
                              void* d_out, int out_size) {
    const float* x = (const float*)d_in[0];   // (N, 2048) fp32
    const float* w = (const float*)d_in[1];   // (64, 2048) fp32
    int n_tokens = in_sizes[0] / DIMK;        // 32768

    float* out      = (float*)d_out;
    float* out_mask = out;                                  // N*64
    float* out_w    = out + (size_t)n_tokens * NEXP;        // N*2
    float* out_i    = out_w + (size_t)n_tokens * 2;         // N*2

    static bool attr_done = false;
    if (!attr_done) {
        cudaFuncSetAttribute(router_mma, cudaFuncAttributeMaxDynamicSharedMemorySize, SMEMB);
        attr_done = true;
    }

    router_mma<<<n_tokens / BM, NT, SMEMB>>>(x, w, out_mask, out_w, out_i);
}

// round 16
// speedup vs baseline: 1.0496x; 1.0496x over previous
#include <cuda_runtime.h>
#include <cuda_bf16.h>
#include <cstdint>

#define DIMK 2048
#define NEXP 64
#define BM   128             // tokens per CTA
#define NT   256             // 8 warps: 2 k-groups x 4 warps (warp tile m32 x n64)
#define KCH  16              // k per chunk
#define NCHG 64              // chunks per group (1024/16)
#define ROWB 48              // padded row bytes (12r mod 32 distinct -> conflict-free ldm)
#define DELTA 1e-4f
#define FCAP 64              // per-CTA flagged-token capacity
#define RSTRIDE4 (32 * (DIMK / 4))   // float4 stride between 32-row groups (16384)

// per-stage layout (bytes within a group region)
#define A_HI 0
#define A_LO 6144
#define B_HI 12288
#define B_LO 15360
#define STAGEB 18432
#define GROUPB (2 * STAGEB)   // 36864 (2 stages)
#define SMEMB  (2 * GROUPB)   // 73728 total dynamic smem
#define RED_STRIDE 68         // reduction row stride in floats

// ---------- helpers ----------
__device__ __forceinline__ uint32_t smem_u32(const void* p) {
    uint32_t a;
    asm("{ .reg .u64 t; cvta.to.shared.u64 t, %1; cvt.u32.u64 %0, t; }" : "=r"(a) : "l"(p));
    return a;
}
__device__ __forceinline__ void gbar(int id) {
    asm volatile("bar.sync %0, %1;" :: "r"(id), "r"(128) : "memory");
}
__device__ __forceinline__ void sts64(uint32_t a, uint32_t x, uint32_t y) {
    asm volatile("st.shared.v2.b32 [%0], {%1,%2};" :: "r"(a), "r"(x), "r"(y) : "memory");
}
__device__ __forceinline__ void ldm4(uint32_t addr, uint32_t* r) {
    asm volatile("ldmatrix.sync.aligned.m8n8.x4.shared.b16 {%0,%1,%2,%3}, [%4];"
                 : "=r"(r[0]), "=r"(r[1]), "=r"(r[2]), "=r"(r[3]) : "r"(addr));
}
__device__ __forceinline__ void mma16(float* c, const uint32_t* a, uint32_t b0, uint32_t b1) {
    asm volatile(
        "mma.sync.aligned.m16n8k16.row.col.f32.bf16.bf16.f32 "
        "{%0,%1,%2,%3}, {%4,%5,%6,%7}, {%8,%9}, {%0,%1,%2,%3};"
        : "+f"(c[0]), "+f"(c[1]), "+f"(c[2]), "+f"(c[3])
        : "r"(a[0]), "r"(a[1]), "r"(a[2]), "r"(a[3]), "r"(b0), "r"(b1));
}
// fp32x4 -> (hi bf16, lo bf16), packed 2 uints each
__device__ __forceinline__ void split4(float4 v, uint32_t* hu, uint32_t* lu) {
    __nv_bfloat16 hx = __float2bfloat16_rn(v.x);
    __nv_bfloat16 hy = __float2bfloat16_rn(v.y);
    __nv_bfloat16 hz = __float2bfloat16_rn(v.z);
    __nv_bfloat16 hw = __float2bfloat16_rn(v.w);
    __nv_bfloat16 lx = __float2bfloat16_rn(v.x - __bfloat162float(hx));
    __nv_bfloat16 ly = __float2bfloat16_rn(v.y - __bfloat162float(hy));
    __nv_bfloat16 lz = __float2bfloat16_rn(v.z - __bfloat162float(hz));
    __nv_bfloat16 lw = __float2bfloat16_rn(v.w - __bfloat162float(hw));
    hu[0] = (uint32_t)__bfloat16_as_ushort(hx) | ((uint32_t)__bfloat16_as_ushort(hy) << 16);
    hu[1] = (uint32_t)__bfloat16_as_ushort(hz) | ((uint32_t)__bfloat16_as_ushort(hw) << 16);
    lu[0] = (uint32_t)__bfloat16_as_ushort(lx) | ((uint32_t)__bfloat16_as_ushort(ly) << 16);
    lu[1] = (uint32_t)__bfloat16_as_ushort(lz) | ((uint32_t)__bfloat16_as_ushort(lw) << 16);
}

struct Top3 { float v0, v1, v2; int i0, i1; };
__device__ __forceinline__ void t3_insert(Top3& t, float v, int i) {
    if (v > t.v0 || (v == t.v0 && i < t.i0)) {
        t.v2 = t.v1; t.v1 = t.v0; t.i1 = t.i0; t.v0 = v; t.i0 = i;
    } else if (v > t.v1 || (v == t.v1 && i < t.i1)) {
        t.v2 = t.v1; t.v1 = v; t.i1 = i;
    } else if (v > t.v2) {
        t.v2 = v;
    }
}
__device__ __forceinline__ void t3_merge_xor(Top3& t, int m) {
    float pv0 = __shfl_xor_sync(0xFFFFFFFFu, t.v0, m);
    float pv1 = __shfl_xor_sync(0xFFFFFFFFu, t.v1, m);
    float pv2 = __shfl_xor_sync(0xFFFFFFFFu, t.v2, m);
    int   pi0 = __shfl_xor_sync(0xFFFFFFFFu, t.i0, m);
    int   pi1 = __shfl_xor_sync(0xFFFFFFFFu, t.i1, m);
    t3_insert(t, pv0, pi0);
    t3_insert(t, pv1, pi1);
    t3_insert(t, pv2, 0x40000000);
}

// =========================================================================
// Single kernel: 3-pass hi/lo bf16 GEMM (2 k-groups, warp tile m32n64),
// coalesced fill, ONE barrier per chunk (STS ; LDG(c+1) ; bar ; compute(c)),
// top-2 epilogue + in-CTA exact repair of low-margin tokens.
// =========================================================================
__global__ __launch_bounds__(NT, 2)
void router_mma(const float* __restrict__ x,
                const float* __restrict__ w,
                float* __restrict__ out_mask,
                float* __restrict__ out_w,
                float* __restrict__ out_i)
{
    extern __shared__ char smem[];
    const uint32_t smb = smem_u32(smem);

    __shared__ int s_cnt;
    __shared__ int s_list[FCAP];

    const int tid   = threadIdx.x;
    const int lane  = tid & 31;
    const int wid   = tid >> 5;        // 0..7
    const int grp   = wid >> 2;        // k-group 0/1
    const int wid_l = wid & 3;         // warp within group
    const int tl    = tid & 127;       // fill id within group
    const int gr    = lane >> 2;
    const int gc    = lane & 3;
    const int mbase = blockIdx.x * BM;
    const int barid = grp + 1;

    if (tid == 0) s_cnt = 0;

    const uint32_t gb = smb + (uint32_t)grp * GROUPB;

    // ---- coalesced fill assignment: 4 lanes per row, 8 rows/warp/instr ----
    const int frow = tl >> 2;          // base row 0..31 (A rows +32q, B rows +32q)
    const int fcol = tl & 3;           // float4 slot within the 64B chunk segment
    const float4* xr = (const float4*)(x + (size_t)(mbase + frow) * DIMK) + grp * 256 + fcol;
    const float4* wr = (const float4*)(w + (size_t)frow * DIMK) + grp * 256 + fcol;
    const uint32_t aQ0 = gb + A_HI + (uint32_t)(frow * ROWB + fcol * 8);
    const uint32_t bQ0 = gb + B_HI + (uint32_t)(frow * ROWB + fcol * 8);

    // ---- ldmatrix lane offsets (proven mapping) ----
    const uint32_t a_off = (uint32_t)((wid_l * 32 + ((lane >> 3) & 1) * 8 + (lane & 7)) * ROWB
                                      + (lane >> 4) * 16);
    const uint32_t b_off = (uint32_t)(((((lane >> 4) & 1) * 8) + (lane & 7)) * ROWB
                                      + ((lane >> 3) & 1) * 16);

    float acc[2][8][4];
#pragma unroll
    for (int i = 0; i < 2; i++)
#pragma unroll
        for (int j = 0; j < 8; j++)
#pragma unroll
            for (int r = 0; r < 4; r++) acc[i][j][r] = 0.0f;

    // ---- prefetch chunk 0 into registers ----
    float4 pa[4], pb[2];
#pragma unroll
    for (int q = 0; q < 4; q++) pa[q] = xr[q * RSTRIDE4];
    pb[0] = wr[0];
    pb[1] = wr[RSTRIDE4];

    // ---- single-barrier pipeline: STS(c) ; LDG(c+1) ; bar ; compute(c) ----
    // Safety (2 stages): a warp reaches bar(c-1) only after its own
    // compute(c-2) and STS(c-1); bar(c-1)-release therefore guarantees all
    // warps finished compute(c-2), which is all STS(c) needs before
    // overwriting stage c&1.
#pragma unroll 1
    for (int c = 0; c < NCHG; c++) {
        const uint32_t stg = (uint32_t)((c & 1) * STAGEB);

        // ---- publish chunk c from registers ----
        {
            uint32_t h[2], l[2];
#pragma unroll
            for (int q = 0; q < 4; q++) {
                split4(pa[q], h, l);
                sts64(aQ0 + (uint32_t)(q * 32 * ROWB) + stg, h[0], h[1]);
                sts64(aQ0 + (uint32_t)(q * 32 * ROWB) + stg + (A_LO - A_HI), l[0], l[1]);
            }
#pragma unroll
            for (int q = 0; q < 2; q++) {
                split4(pb[q], h, l);
                sts64(bQ0 + (uint32_t)(q * 32 * ROWB) + stg, h[0], h[1]);
                sts64(bQ0 + (uint32_t)(q * 32 * ROWB) + stg + (B_LO - B_HI), l[0], l[1]);
            }
        }

        // ---- prefetch chunk c+1 (no ordering requirement; hides under bar) ----
        if (c + 1 < NCHG) {
#pragma unroll
            for (int q = 0; q < 4; q++) pa[q] = xr[(c + 1) * 4 + q * RSTRIDE4];
            pb[0] = wr[(c + 1) * 4];
            pb[1] = wr[(c + 1) * 4 + RSTRIDE4];
        }

        gbar(barid);

        // ---- compute: one k16 step, 3 passes ----
        const uint32_t abase = gb + stg + A_HI + a_off;
        const uint32_t bbase = gb + stg + B_HI + b_off;
        uint32_t ah[2][4], al[2][4];
#pragma unroll
        for (int i = 0; i < 2; i++) {
            ldm4(abase + (uint32_t)(i * 16 * ROWB), ah[i]);
            ldm4(abase + (uint32_t)(i * 16 * ROWB) + (A_LO - A_HI), al[i]);
        }
#pragma unroll
        for (int jp = 0; jp < 4; jp++) {
            uint32_t th[4], tl4[4];
            ldm4(bbase + (uint32_t)(jp * 16 * ROWB), th);
            ldm4(bbase + (uint32_t)(jp * 16 * ROWB) + (B_LO - B_HI), tl4);
#pragma unroll
            for (int i = 0; i < 2; i++) {
                mma16(acc[i][2 * jp],     ah[i], th[0],  th[1]);    // hh
                mma16(acc[i][2 * jp],     al[i], th[0],  th[1]);    // lh
                mma16(acc[i][2 * jp],     ah[i], tl4[0], tl4[1]);   // hl
                mma16(acc[i][2 * jp + 1], ah[i], th[2],  th[3]);
                mma16(acc[i][2 * jp + 1], al[i], th[2],  th[3]);
                mma16(acc[i][2 * jp + 1], ah[i], tl4[2], tl4[3]);
            }
        }
    }

    // ---- cross-group reduction (group 1 -> smem -> group 0 adds) ----
    __syncthreads();
    float* redf = (float*)(smem + GROUPB);
    if (grp == 1) {
#pragma unroll
        for (int i = 0; i < 2; i++)
#pragma unroll
            for (int rh = 0; rh < 2; rh++) {
                const int ml = wid_l * 32 + i * 16 + rh * 8 + gr;
#pragma unroll
                for (int j = 0; j < 8; j++) {
                    float2 v = make_float2(acc[i][j][rh * 2], acc[i][j][rh * 2 + 1]);
                    *(float2*)(redf + ml * RED_STRIDE + 8 * j + 2 * gc) = v;
                }
            }
    }
    __syncthreads();
    if (grp == 0) {
#pragma unroll
        for (int i = 0; i < 2; i++)
#pragma unroll
            for (int rh = 0; rh < 2; rh++) {
                const int ml = wid_l * 32 + i * 16 + rh * 8 + gr;
#pragma unroll
                for (int j = 0; j < 8; j++) {
                    float2 v = *(float2*)(redf + ml * RED_STRIDE + 8 * j + 2 * gc);
                    acc[i][j][rh * 2]     += v.x;
                    acc[i][j][rh * 2 + 1] += v.y;
                }
            }

        // ---- epilogue: top-2 + smem flags + outputs ----
#pragma unroll
        for (int i = 0; i < 2; i++) {
#pragma unroll
            for (int rh = 0; rh < 2; rh++) {
                const int m = wid_l * 32 + i * 16 + rh * 8 + gr;
                Top3 t; t.v0 = -1e30f; t.v1 = -1e30f; t.v2 = -1e30f; t.i0 = 0; t.i1 = 0;
#pragma unroll
                for (int j = 0; j < 8; j++) {
#pragma unroll
                    for (int b = 0; b < 2; b++)
                        t3_insert(t, acc[i][j][rh * 2 + b], 8 * j + 2 * gc + b);
                }
                t3_merge_xor(t, 1);
                t3_merge_xor(t, 2);

                const size_t g = (size_t)(mbase + m);
                if (gc == 0) {
                    float e1  = expf(t.v1 - t.v0);
                    float inv = 1.0f / (1.0f + e1);
                    out_w[g * 2 + 0] = inv;
                    out_w[g * 2 + 1] = e1 * inv;
                    out_i[g * 2 + 0] = (float)t.i0;
                    out_i[g * 2 + 1] = (float)t.i1;
                    if ((t.v0 - t.v1 < DELTA) || (t.v1 - t.v2 < DELTA)) {
                        int slot = atomicAdd(&s_cnt, 1);
                        if (slot < FCAP) s_list[slot] = m;
                    }
                }
                float* mrow = out_mask + g * NEXP + gc * 16;
#pragma unroll
                for (int q = 0; q < 4; q++) {
                    int e0 = gc * 16 + q * 4;
                    float4 mv;
                    mv.x = (e0 + 0 == t.i0 || e0 + 0 == t.i1) ? 1.0f : 0.0f;
                    mv.y = (e0 + 1 == t.i0 || e0 + 1 == t.i1) ? 1.0f : 0.0f;
                    mv.z = (e0 + 2 == t.i0 || e0 + 2 == t.i1) ? 1.0f : 0.0f;
                    mv.w = (e0 + 3 == t.i0 || e0 + 3 == t.i1) ? 1.0f : 0.0f;
                    *(float4*)(mrow + q * 4) = mv;
                }
            }
        }
    }

    // ================= in-CTA exact repair of flagged tokens =================
    __syncthreads();
    int cnt = s_cnt;
    if (cnt > FCAP) cnt = FCAP;
    if (cnt > 0) {
        float* xs = (float*)smem;            // 8KB, stage area is dead now
        float* lg = (float*)(smem + 8192);   // 64 floats
        const int e    = tid >> 2;           // expert
        const int part = tid & 3;            // interleaved float4 k-part

        for (int it = 0; it < cnt; it++) {
            const int m = s_list[it];
            const size_t tok = (size_t)(mbase + m);
            __syncthreads();
            {
                const float4* xrow = (const float4*)(x + tok * DIMK);
                for (int q = tid; q < DIMK / 4; q += NT)
                    ((float4*)xs)[q] = xrow[q];
            }
            __syncthreads();

            const float4* wrow = (const float4*)(w + (size_t)e * DIMK);
            const float4* xp   = (const float4*)xs;
            float4 accv = make_float4(0, 0, 0, 0);
#pragma unroll 8
            for (int q = 0; q < 128; q++) {
                float4 xv = xp[4 * q + part];
                float4 wv = wrow[4 * q + part];
                accv.x = fmaf(xv.x, wv.x, accv.x);
                accv.y = fmaf(xv.y, wv.y, accv.y);
                accv.z = fmaf(xv.z, wv.z, accv.z);
                accv.w = fmaf(xv.w, wv.w, accv.w);
            }
            float s = (accv.x + accv.y) + (accv.z + accv.w);
            s += __shfl_xor_sync(0xFFFFFFFFu, s, 1);
            s += __shfl_xor_sync(0xFFFFFFFFu, s, 2);
            if (part == 0) lg[e] = s;
            __syncthreads();

            if (tid < 32) {
                Top3 t; t.v0 = -1e30f; t.v1 = -1e30f; t.v2 = -1e30f; t.i0 = 0; t.i1 = 0;
                t3_insert(t, lg[tid], tid);
                t3_insert(t, lg[tid + 32], tid + 32);
                t3_merge_xor(t, 1);
                t3_merge_xor(t, 2);
                t3_merge_xor(t, 4);
                t3_merge_xor(t, 8);
                t3_merge_xor(t, 16);

                int i0 = __shfl_sync(0xFFFFFFFFu, t.i0, 0);
                int i1 = __shfl_sync(0xFFFFFFFFu, t.i1, 0);
                if (tid == 0) {
                    float e1  = expf(t.v1 - t.v0);
                    float inv = 1.0f / (1.0f + e1);
                    out_w[tok * 2 + 0] = inv;
                    out_w[tok * 2 + 1] = e1 * inv;
                    out_i[tok * 2 + 0] = (float)i0;
                    out_i[tok * 2 + 1] = (float)i1;
                }
                out_mask[tok * NEXP + tid] =
                    (tid == i0 || tid == i1) ? 1.0f : 0.0f;
                out_mask[tok * NEXP + tid + 32] =
                    (tid + 32 == i0 || tid + 32 == i1) ? 1.0f : 0.0f;
            }
        }
    }
}

extern "C" void kernel_launch(void* const* d_in, const int* in_sizes, int n_in,
                              void* d_out, int out_size) {
    const float* x = (const float*)d_in[0];   // (N, 2048) fp32
    const float* w = (const float*)d_in[1];   // (64, 2048) fp32
    int n_tokens = in_sizes[0] / DIMK;        // 32768

    float* out      = (float*)d_out;
    float* out_mask = out;                                  // N*64
    float* out_w    = out + (size_t)n_tokens * NEXP;        // N*2
    float* out_i    = out_w + (size_t)n_tokens * 2;         // N*2

    static bool attr_done = false;
    if (!attr_done) {
        cudaFuncSetAttribute(router_mma, cudaFuncAttributeMaxDynamicSharedMemorySize, SMEMB);
        attr_done = true;
    }

    router_mma<<<n_tokens / BM, NT, SMEMB>>>(x, w, out_mask, out_w, out_i);
}

// round 17
// speedup vs baseline: 1.3228x; 1.2603x over previous
#include <cuda_runtime.h>
#include <cuda_bf16.h>
#include <cstdint>

#define DIMK 2048
#define NEXP 64
#define BM   128             // tokens per CTA
#define NT   256             // 8 warps: 2 k-groups x 4 warps (warp tile m32 x n64)
#define KCH  16              // k per chunk
#define NCHG 64              // chunks per group (1024/16)
#define ROWB 48              // padded row bytes (12r mod 32 distinct -> conflict-free ldm)
#define DELTA 1e-4f
#define FCAP 64              // per-CTA flagged-token capacity
#define RSTRIDE4 (32 * (DIMK / 4))   // float4 stride between 32-row groups (16384)

// per-stage layout (bytes within a group region)
#define A_HI 0
#define A_LO 6144
#define B_HI 12288
#define B_LO 15360
#define STAGEB 18432
#define GROUPB (2 * STAGEB)   // 36864 (2 stages)
#define SMEMB  (2 * GROUPB)   // 73728 total dynamic smem
#define RED_STRIDE 68         // reduction row stride in floats

// Pre-split W, packed per (group, chunk): [g][c][row0..63][16 bf16]
// Main-kernel B fill = 1 coalesced LDG.128 + 1 STS.128 per hi/lo per thread.
__device__ __align__(16) __nv_bfloat16 WH[2][NCHG][NEXP][KCH];   // 256KB
__device__ __align__(16) __nv_bfloat16 WL[2][NCHG][NEXP][KCH];   // 256KB

// ---------- helpers ----------
__device__ __forceinline__ uint32_t smem_u32(const void* p) {
    uint32_t a;
    asm("{ .reg .u64 t; cvta.to.shared.u64 t, %1; cvt.u32.u64 %0, t; }" : "=r"(a) : "l"(p));
    return a;
}
__device__ __forceinline__ void gbar(int id) {
    asm volatile("bar.sync %0, %1;" :: "r"(id), "r"(128) : "memory");
}
__device__ __forceinline__ void sts64(uint32_t a, uint32_t x, uint32_t y) {
    asm volatile("st.shared.v2.b32 [%0], {%1,%2};" :: "r"(a), "r"(x), "r"(y) : "memory");
}
__device__ __forceinline__ void sts128(uint32_t a, uint32_t x, uint32_t y, uint32_t z, uint32_t w) {
    asm volatile("st.shared.v4.b32 [%0], {%1,%2,%3,%4};" :: "r"(a), "r"(x), "r"(y), "r"(z), "r"(w) : "memory");
}
__device__ __forceinline__ void ldm4(uint32_t addr, uint32_t* r) {
    asm volatile("ldmatrix.sync.aligned.m8n8.x4.shared.b16 {%0,%1,%2,%3}, [%4];"
                 : "=r"(r[0]), "=r"(r[1]), "=r"(r[2]), "=r"(r[3]) : "r"(addr));
}
__device__ __forceinline__ void mma16(float* c, const uint32_t* a, uint32_t b0, uint32_t b1) {
    asm volatile(
        "mma.sync.aligned.m16n8k16.row.col.f32.bf16.bf16.f32 "
        "{%0,%1,%2,%3}, {%4,%5,%6,%7}, {%8,%9}, {%0,%1,%2,%3};"
        : "+f"(c[0]), "+f"(c[1]), "+f"(c[2]), "+f"(c[3])
        : "r"(a[0]), "r"(a[1]), "r"(a[2]), "r"(a[3]), "r"(b0), "r"(b1));
}
// fp32x4 -> (hi bf16x2 pair, lo bf16x2 pair) via packed cvt; bitwise identical
// to per-element __float2bfloat16_rn splitting.
__device__ __forceinline__ void split4b(float4 v, uint32_t* hu, uint32_t* lu) {
    asm("cvt.rn.bf16x2.f32 %0, %1, %2;" : "=r"(hu[0]) : "f"(v.y), "f"(v.x));
    asm("cvt.rn.bf16x2.f32 %0, %1, %2;" : "=r"(hu[1]) : "f"(v.w), "f"(v.z));
    float fx = __uint_as_float(hu[0] << 16);
    float fy = __uint_as_float(hu[0] & 0xFFFF0000u);
    float fz = __uint_as_float(hu[1] << 16);
    float fw = __uint_as_float(hu[1] & 0xFFFF0000u);
    asm("cvt.rn.bf16x2.f32 %0, %1, %2;" : "=r"(lu[0]) : "f"(v.y - fy), "f"(v.x - fx));
    asm("cvt.rn.bf16x2.f32 %0, %1, %2;" : "=r"(lu[1]) : "f"(v.w - fw), "f"(v.z - fz));
}

struct Top3 { float v0, v1, v2; int i0, i1; };
__device__ __forceinline__ void t3_insert(Top3& t, float v, int i) {
    if (v > t.v0 || (v == t.v0 && i < t.i0)) {
        t.v2 = t.v1; t.v1 = t.v0; t.i1 = t.i0; t.v0 = v; t.i0 = i;
    } else if (v > t.v1 || (v == t.v1 && i < t.i1)) {
        t.v2 = t.v1; t.v1 = v; t.i1 = i;
    } else if (v > t.v2) {
        t.v2 = v;
    }
}
__device__ __forceinline__ void t3_merge_xor(Top3& t, int m) {
    float pv0 = __shfl_xor_sync(0xFFFFFFFFu, t.v0, m);
    float pv1 = __shfl_xor_sync(0xFFFFFFFFu, t.v1, m);
    float pv2 = __shfl_xor_sync(0xFFFFFFFFu, t.v2, m);
    int   pi0 = __shfl_xor_sync(0xFFFFFFFFu, t.i0, m);
    int   pi1 = __shfl_xor_sync(0xFFFFFFFFu, t.i1, m);
    t3_insert(t, pv0, pi0);
    t3_insert(t, pv1, pi1);
    t3_insert(t, pv2, 0x40000000);
}

// =========================================================================
// Pre-split kernel: W fp32 -> packed hi/lo bf16 blobs (identical rounding
// to the old in-loop split4).
// =========================================================================
__global__ __launch_bounds__(256)
void presplit_w(const float* __restrict__ w)
{
    int idx = blockIdx.x * blockDim.x + threadIdx.x;   // pair index
    if (idx >= NEXP * DIMK / 2) return;
    int e2  = idx * 2;
    int row = e2 >> 11;            // / DIMK
    int k   = e2 & (DIMK - 1);
    float vx = w[(size_t)row * DIMK + k];
    float vy = w[(size_t)row * DIMK + k + 1];
    __nv_bfloat16 hx = __float2bfloat16_rn(vx);
    __nv_bfloat16 hy = __float2bfloat16_rn(vy);
    __nv_bfloat16 lx = __float2bfloat16_rn(vx - __bfloat162float(hx));
    __nv_bfloat16 ly = __float2bfloat16_rn(vy - __bfloat162float(hy));
    int g = k >> 10, kk = k & 1023, c = kk >> 4, p = kk & 15;   // p even
    uint32_t hv = (uint32_t)__bfloat16_as_ushort(hx) | ((uint32_t)__bfloat16_as_ushort(hy) << 16);
    uint32_t lv = (uint32_t)__bfloat16_as_ushort(lx) | ((uint32_t)__bfloat16_as_ushort(ly) << 16);
    *(uint32_t*)&WH[g][c][row][p] = hv;
    *(uint32_t*)&WL[g][c][row][p] = lv;
}

// =========================================================================
// Main kernel: 3-pass hi/lo bf16 GEMM (2 k-groups, warp tile m32n64),
// coalesced A fill + pre-split packed B fill, one barrier per chunk,
// top-2 epilogue + in-CTA exact repair.
// =========================================================================
__global__ __launch_bounds__(NT, 2)
void router_mma(const float* __restrict__ x,
                const float* __restrict__ w,
                float* __restrict__ out_mask,
                float* __restrict__ out_w,
                float* __restrict__ out_i)
{
    extern __shared__ char smem[];
    const uint32_t smb = smem_u32(smem);

    __shared__ int s_cnt;
    __shared__ int s_list[FCAP];

    const int tid   = threadIdx.x;
    const int lane  = tid & 31;
    const int wid   = tid >> 5;        // 0..7
    const int grp   = wid >> 2;        // k-group 0/1
    const int wid_l = wid & 3;         // warp within group
    const int tl    = tid & 127;       // fill id within group
    const int gr    = lane >> 2;
    const int gc    = lane & 3;
    const int mbase = blockIdx.x * BM;
    const int barid = grp + 1;

    if (tid == 0) s_cnt = 0;

    const uint32_t gb = smb + (uint32_t)grp * GROUPB;

    // ---- A fill: 4 lanes per row, coalesced ----
    const int frow = tl >> 2;
    const int fcol = tl & 3;
    const float4* xr = (const float4*)(x + (size_t)(mbase + frow) * DIMK) + grp * 256 + fcol;
    const uint32_t aQ0 = gb + A_HI + (uint32_t)(frow * ROWB + fcol * 8);

    // ---- B fill: packed pre-split blobs; 128 uint4 per chunk per blob ----
    const uint4* whp = ((const uint4*)WH) + (size_t)grp * NCHG * 128;
    const uint4* wlp = ((const uint4*)WL) + (size_t)grp * NCHG * 128;
    const uint32_t bQ0 = gb + B_HI + (uint32_t)((tl >> 1) * ROWB + (tl & 1) * 16);

    // ---- ldmatrix lane offsets (proven mapping) ----
    const uint32_t a_off = (uint32_t)((wid_l * 32 + ((lane >> 3) & 1) * 8 + (lane & 7)) * ROWB
                                      + (lane >> 4) * 16);
    const uint32_t b_off = (uint32_t)(((((lane >> 4) & 1) * 8) + (lane & 7)) * ROWB
                                      + ((lane >> 3) & 1) * 16);

    float acc[2][8][4];
#pragma unroll
    for (int i = 0; i < 2; i++)
#pragma unroll
        for (int j = 0; j < 8; j++)
#pragma unroll
            for (int r = 0; r < 4; r++) acc[i][j][r] = 0.0f;

    // ---- prefetch chunk 0 ----
    float4 pa[4];
    uint4 pbh, pbl;
#pragma unroll
    for (int q = 0; q < 4; q++) pa[q] = xr[q * RSTRIDE4];
    pbh = whp[tl];
    pbl = wlp[tl];

    // ---- single-barrier pipeline: STS(c) ; LDG(c+1) ; bar ; compute(c) ----
#pragma unroll 1
    for (int c = 0; c < NCHG; c++) {
        const uint32_t stg = (uint32_t)((c & 1) * STAGEB);

        // ---- publish chunk c ----
        {
            uint32_t h[2], l[2];
#pragma unroll
            for (int q = 0; q < 4; q++) {
                split4b(pa[q], h, l);
                sts64(aQ0 + (uint32_t)(q * 32 * ROWB) + stg, h[0], h[1]);
                sts64(aQ0 + (uint32_t)(q * 32 * ROWB) + stg + (A_LO - A_HI), l[0], l[1]);
            }
            sts128(bQ0 + stg, pbh.x, pbh.y, pbh.z, pbh.w);
            sts128(bQ0 + stg + (B_LO - B_HI), pbl.x, pbl.y, pbl.z, pbl.w);
        }

        // ---- prefetch chunk c+1 (hides under bar + compute) ----
        if (c + 1 < NCHG) {
#pragma unroll
            for (int q = 0; q < 4; q++) pa[q] = xr[(c + 1) * 4 + q * RSTRIDE4];
            pbh = whp[(c + 1) * 128 + tl];
            pbl = wlp[(c + 1) * 128 + tl];
        }

        gbar(barid);

        // ---- compute: one k16 step, 3 passes ----
        const uint32_t abase = gb + stg + A_HI + a_off;
        const uint32_t bbase = gb + stg + B_HI + b_off;
        uint32_t ah[2][4], al[2][4];
#pragma unroll
        for (int i = 0; i < 2; i++) {
            ldm4(abase + (uint32_t)(i * 16 * ROWB), ah[i]);
            ldm4(abase + (uint32_t)(i * 16 * ROWB) + (A_LO - A_HI), al[i]);
        }
#pragma unroll
        for (int jp = 0; jp < 4; jp++) {
            uint32_t th[4], tl4[4];
            ldm4(bbase + (uint32_t)(jp * 16 * ROWB), th);
            ldm4(bbase + (uint32_t)(jp * 16 * ROWB) + (B_LO - B_HI), tl4);
#pragma unroll
            for (int i = 0; i < 2; i++) {
                mma16(acc[i][2 * jp],     ah[i], th[0],  th[1]);    // hh
                mma16(acc[i][2 * jp],     al[i], th[0],  th[1]);    // lh
                mma16(acc[i][2 * jp],     ah[i], tl4[0], tl4[1]);   // hl
                mma16(acc[i][2 * jp + 1], ah[i], th[2],  th[3]);
                mma16(acc[i][2 * jp + 1], al[i], th[2],  th[3]);
                mma16(acc[i][2 * jp + 1], ah[i], tl4[2], tl4[3]);
            }
        }
    }

    // ---- cross-group reduction (group 1 -> smem -> group 0 adds) ----
    __syncthreads();
    float* redf = (float*)(smem + GROUPB);
    if (grp == 1) {
#pragma unroll
        for (int i = 0; i < 2; i++)
#pragma unroll
            for (int rh = 0; rh < 2; rh++) {
                const int ml = wid_l * 32 + i * 16 + rh * 8 + gr;
#pragma unroll
                for (int j = 0; j < 8; j++) {
                    float2 v = make_float2(acc[i][j][rh * 2], acc[i][j][rh * 2 + 1]);
                    *(float2*)(redf + ml * RED_STRIDE + 8 * j + 2 * gc) = v;
                }
            }
    }
    __syncthreads();
    if (grp == 0) {
#pragma unroll
        for (int i = 0; i < 2; i++)
#pragma unroll
            for (int rh = 0; rh < 2; rh++) {
                const int ml = wid_l * 32 + i * 16 + rh * 8 + gr;
#pragma unroll
                for (int j = 0; j < 8; j++) {
                    float2 v = *(float2*)(redf + ml * RED_STRIDE + 8 * j + 2 * gc);
                    acc[i][j][rh * 2]     += v.x;
                    acc[i][j][rh * 2 + 1] += v.y;
                }
            }

        // ---- epilogue: top-2 + smem flags + outputs ----
#pragma unroll
        for (int i = 0; i < 2; i++) {
#pragma unroll
            for (int rh = 0; rh < 2; rh++) {
                const int m = wid_l * 32 + i * 16 + rh * 8 + gr;
                Top3 t; t.v0 = -1e30f; t.v1 = -1e30f; t.v2 = -1e30f; t.i0 = 0; t.i1 = 0;
#pragma unroll
                for (int j = 0; j < 8; j++) {
#pragma unroll
                    for (int b = 0; b < 2; b++)
                        t3_insert(t, acc[i][j][rh * 2 + b], 8 * j + 2 * gc + b);
                }
                t3_merge_xor(t, 1);
                t3_merge_xor(t, 2);

                const size_t g = (size_t)(mbase + m);
                if (gc == 0) {
                    float e1  = expf(t.v1 - t.v0);
                    float inv = 1.0f / (1.0f + e1);
                    out_w[g * 2 + 0] = inv;
                    out_w[g * 2 + 1] = e1 * inv;
                    out_i[g * 2 + 0] = (float)t.i0;
                    out_i[g * 2 + 1] = (float)t.i1;
                    if ((t.v0 - t.v1 < DELTA) || (t.v1 - t.v2 < DELTA)) {
                        int slot = atomicAdd(&s_cnt, 1);
                        if (slot < FCAP) s_list[slot] = m;
                    }
                }
                float* mrow = out_mask + g * NEXP + gc * 16;
#pragma unroll
                for (int q = 0; q < 4; q++) {
                    int e0 = gc * 16 + q * 4;
                    float4 mv;
                    mv.x = (e0 + 0 == t.i0 || e0 + 0 == t.i1) ? 1.0f : 0.0f;
                    mv.y = (e0 + 1 == t.i0 || e0 + 1 == t.i1) ? 1.0f : 0.0f;
                    mv.z = (e0 + 2 == t.i0 || e0 + 2 == t.i1) ? 1.0f : 0.0f;
                    mv.w = (e0 + 3 == t.i0 || e0 + 3 == t.i1) ? 1.0f : 0.0f;
                    *(float4*)(mrow + q * 4) = mv;
                }
            }
        }
    }

    // ================= in-CTA exact repair of flagged tokens =================
    __syncthreads();
    int cnt = s_cnt;
    if (cnt > FCAP) cnt = FCAP;
    if (cnt > 0) {
        float* xs = (float*)smem;            // 8KB, stage area is dead now
        float* lg = (float*)(smem + 8192);   // 64 floats
        const int e    = tid >> 2;           // expert
        const int part = tid & 3;            // interleaved float4 k-part

        for (int it = 0; it < cnt; it++) {
            const int m = s_list[it];
            const size_t tok = (size_t)(mbase + m);
            __syncthreads();
            {
                const float4* xrow = (const float4*)(x + tok * DIMK);
                for (int q = tid; q < DIMK / 4; q += NT)
                    ((float4*)xs)[q] = xrow[q];
            }
            __syncthreads();

            const float4* wrow = (const float4*)(w + (size_t)e * DIMK);
            const float4* xp   = (const float4*)xs;
            float4 accv = make_float4(0, 0, 0, 0);
#pragma unroll 8
            for (int q = 0; q < 128; q++) {
                float4 xv = xp[4 * q + part];
                float4 wv = wrow[4 * q + part];
                accv.x = fmaf(xv.x, wv.x, accv.x);
                accv.y = fmaf(xv.y, wv.y, accv.y);
                accv.z = fmaf(xv.z, wv.z, accv.z);
                accv.w = fmaf(xv.w, wv.w, accv.w);
            }
            float s = (accv.x + accv.y) + (accv.z + accv.w);
            s += __shfl_xor_sync(0xFFFFFFFFu, s, 1);
            s += __shfl_xor_sync(0xFFFFFFFFu, s, 2);
            if (part == 0) lg[e] = s;
            __syncthreads();

            if (tid < 32) {
                Top3 t; t.v0 = -1e30f; t.v1 = -1e30f; t.v2 = -1e30f; t.i0 = 0; t.i1 = 0;
                t3_insert(t, lg[tid], tid);
                t3_insert(t, lg[tid + 32], tid + 32);
                t3_merge_xor(t, 1);
                t3_merge_xor(t, 2);
                t3_merge_xor(t, 4);
                t3_merge_xor(t, 8);
                t3_merge_xor(t, 16);

                int i0 = __shfl_sync(0xFFFFFFFFu, t.i0, 0);
                int i1 = __shfl_sync(0xFFFFFFFFu, t.i1, 0);
                if (tid == 0) {
                    float e1  = expf(t.v1 - t.v0);
                    float inv = 1.0f / (1.0f + e1);
                    out_w[tok * 2 + 0] = inv;
                    out_w[tok * 2 + 1] = e1 * inv;
                    out_i[tok * 2 + 0] = (float)i0;
                    out_i[tok * 2 + 1] = (float)i1;
                }
                out_mask[tok * NEXP + tid] =
                    (tid == i0 || tid == i1) ? 1.0f : 0.0f;
                out_mask[tok * NEXP + tid + 32] =
                    (tid + 32 == i0 || tid + 32 == i1) ? 1.0f : 0.0f;
            }
        }
    }
}

extern "C" void kernel_launch(void* const* d_in, const int* in_sizes, int n_in,
                              void* d_out, int out_size) {
    const float* x = (const float*)d_in[0];   // (N, 2048) fp32
    const float* w = (const float*)d_in[1];   // (64, 2048) fp32
    int n_tokens = in_sizes[0] / DIMK;        // 32768

    float* out      = (float*)d_out;
    float* out_mask = out;                                  // N*64
    float* out_w    = out + (size_t)n_tokens * NEXP;        // N*2
    float* out_i    = out_w + (size_t)n_tokens * 2;         // N*2

    static bool attr_done = false;
    if (!attr_done) {
        cudaFuncSetAttribute(router_mma, cudaFuncAttributeMaxDynamicSharedMemorySize, SMEMB);
        attr_done = true;
    }

    presplit_w<<<(NEXP * DIMK / 2 + 255) / 256, 256>>>(w);
    router_mma<<<n_tokens / BM, NT, SMEMB>>>(x, w, out_mask, out_w, out_i);
}